// round 16
// baseline (speedup 1.0000x reference)
#include <cuda_runtime.h>

// Problem constants
#define Bn 32
#define Cc 3
#define Hd 384
#define Wd 640
#define HW (Hd * Wd)

// Tiling
#define TW 128      // output cols per block
#define TH 16       // output rows per block
#define PH 18       // padded rows (TH + 2)
#define PWs 132     // smem row stride in float2: 128 interior + 2 halo + 2 pad
#define RPT 8       // rows per thread (TH / 2)

typedef unsigned long long u64t;

__device__ __forceinline__ int reflect1(int i, int n) {
    // jnp.pad mode='reflect', pad=1: -1 -> 1, n -> n-2
    if (i < 0) i = -i;
    if (i >= n) i = 2 * n - 2 - i;
    return i;
}

// ---- packed f32x2 helpers (FADD2/FMUL2/FFMA2 — PTX-only on sm_103a) ----
__device__ __forceinline__ u64t f2p(float2 v) {
    u64t r; asm("mov.b64 %0, {%1, %2};" : "=l"(r) : "f"(v.x), "f"(v.y)); return r;
}
__device__ __forceinline__ float2 p2f(u64t p) {
    float2 v; asm("mov.b64 {%0, %1}, %2;" : "=f"(v.x), "=f"(v.y) : "l"(p)); return v;
}
__device__ __forceinline__ u64t addx2(u64t a, u64t b) {
    u64t r; asm("add.rn.f32x2 %0, %1, %2;" : "=l"(r) : "l"(a), "l"(b)); return r;
}
__device__ __forceinline__ u64t mulx2(u64t a, u64t b) {
    u64t r; asm("mul.rn.f32x2 %0, %1, %2;" : "=l"(r) : "l"(a), "l"(b)); return r;
}
__device__ __forceinline__ u64t fmax2(u64t a, u64t b, u64t c) {
    u64t r; asm("fma.rn.f32x2 %0, %1, %2, %3;" : "=l"(r) : "l"(a), "l"(b), "l"(c)); return r;
}

__global__ __launch_bounds__(256, 3)
void recon_loss_kernel(const float* __restrict__ X,
                       const float* __restrict__ Y,
                       float* __restrict__ out) {
    // Interleaved (x,y) tile. Layout: j=0..127 interior (global col w0+j),
    // j=128 left-halo (w0-1), j=129 right-halo (w0+128).
    __shared__ float2 s[PH][PWs];

    const int w0 = blockIdx.x * TW;
    const int h0 = blockIdx.y * TH;
    const int b  = blockIdx.z;
    const int tid = threadIdx.x;
    const int col = tid & (TW - 1);        // 0..127
    const int row_base = (tid >> 7) * RPT; // 0 or 8

    // ---- read indices (computed once) ----
    const int jL = (col > 0)   ? col - 1 : 128;
    const int jR = (col < 127) ? col + 1 : 129;

    // ---- staging geometry (computed once, reused for all channels) ----
    // Interior: 18 rows x 32 float4-chunks = 576 slots; thread covers
    // rows ir0, ir0+8, ir0+16 (third only for tid<64) at chunk c4.
    const int c4  = tid & 31;                  // chunk index 0..31
    const int ir0 = tid >> 5;                  // base padded row 0..7
    const int gc4 = w0 + 4 * c4;               // aligned global col (mult of 4)
    const int ro0 = reflect1(h0 - 1 + ir0,      Hd) * Wd + gc4;
    const int ro1 = reflect1(h0 - 1 + ir0 + 8,  Hd) * Wd + gc4;
    const int ro2 = reflect1(h0 - 1 + ir0 + 16, Hd) * Wd + gc4;  // tid<64 only
    const bool third = tid < 64;
    // Halo: 36 threads cover 2 cols x 18 rows.
    const bool tail = tid < 36;
    const int ti = tid >> 1;
    const int tj = 128 + (tid & 1);
    const int tg = reflect1(h0 - 1 + ti, Hd) * Wd
                 + reflect1((tid & 1) ? w0 + 128 : w0 - 1, Wd);

    const float KC  = 526.7025f;    // 81*C1 == 9*C2
    const float KC9 = 4740.3225f;   // 81*C2

    float acc[RPT];
#pragma unroll
    for (int i = 0; i < RPT; i++) acc[i] = 0.0f;

    for (int c = 0; c < Cc; c++) {
        const float* __restrict__ xb = X + (size_t)(b * Cc + c) * HW;
        const float* __restrict__ yb = Y + (size_t)(b * Cc + c) * HW;

        __syncthreads();   // everyone done reading previous channel's tile

        // ---- stage: LDG.128 pairs, interleave in regs, STS.128 ----
        float4 xv0 = *(const float4*)(xb + ro0);
        float4 yv0 = *(const float4*)(yb + ro0);
        float4 xv1 = *(const float4*)(xb + ro1);
        float4 yv1 = *(const float4*)(yb + ro1);
        float4 xv2, yv2;
        if (third) { xv2 = *(const float4*)(xb + ro2);
                     yv2 = *(const float4*)(yb + ro2); }
        float2 tx;
        if (tail) tx = make_float2(xb[tg], yb[tg]);

        {
            const int j0 = 4 * c4;
            *(float4*)&s[ir0][j0]          = make_float4(xv0.x, yv0.x, xv0.y, yv0.y);
            *(float4*)&s[ir0][j0 + 2]      = make_float4(xv0.z, yv0.z, xv0.w, yv0.w);
            *(float4*)&s[ir0 + 8][j0]      = make_float4(xv1.x, yv1.x, xv1.y, yv1.y);
            *(float4*)&s[ir0 + 8][j0 + 2]  = make_float4(xv1.z, yv1.z, xv1.w, yv1.w);
            if (third) {
                *(float4*)&s[ir0 + 16][j0]     = make_float4(xv2.x, yv2.x, xv2.y, yv2.y);
                *(float4*)&s[ir0 + 16][j0 + 2] = make_float4(xv2.z, yv2.z, xv2.w, yv2.w);
            }
        }
        if (tail) s[ti][tj] = tx;
        __syncthreads();

        // ---- compute: rolling horizontal row-sums (ring of 3) ----
        //   rs_s = packed (sum x, sum y); rs_q = sum(x^2+y^2); rs_xy = sum x*y
        u64t  rs_s[3];
        float rs_q[3], rs_xy[3], dv_prev;

#pragma unroll
        for (int k = 0; k < 2; k++) {
            int pr = row_base + k;
            float2 v0 = s[pr][jL], v1 = s[pr][col], v2 = s[pr][jR];
            u64t p0 = f2p(v0), p1 = f2p(v1), p2 = f2p(v2);
            rs_s[k] = addx2(addx2(p0, p1), p2);
            float2 q = p2f(fmax2(p2, p2, fmax2(p1, p1, mulx2(p0, p0))));
            rs_q[k]  = q.x + q.y;
            rs_xy[k] = fmaf(v0.x, v0.y, fmaf(v1.x, v1.y, v2.x * v2.y));
            if (k == 1) dv_prev = v1.x - v1.y;   // center row for h=0
        }

#pragma unroll
        for (int h = 0; h < RPT; h++) {
            const int kn = (h + 2) % 3;   // slot for the new (bottom) row
            int pr = row_base + h + 2;
            float2 v0 = s[pr][jL], v1 = s[pr][col], v2 = s[pr][jR];
            u64t p0 = f2p(v0), p1 = f2p(v1), p2 = f2p(v2);
            rs_s[kn] = addx2(addx2(p0, p1), p2);
            float2 q = p2f(fmax2(p2, p2, fmax2(p1, p1, mulx2(p0, p0))));
            rs_q[kn]  = q.x + q.y;
            rs_xy[kn] = fmaf(v0.x, v0.y, fmaf(v1.x, v1.y, v2.x * v2.y));

            // 3x3 window sums
            float2 S = p2f(addx2(addx2(rs_s[0], rs_s[1]), rs_s[2]));
            float Sx  = S.x;
            float Sy  = S.y;
            float Sq  = rs_q[0]  + rs_q[1]  + rs_q[2];   // Sxx + Syy
            float Sxy = rs_xy[0] + rs_xy[1] + rs_xy[2];

            // Scaled-through SSIM (exact rearrangement; uses C2 = 9*C1):
            //   ns = 0.5 - (P*Q)/(R*T)/18
            float t = Sx * Sy;
            float P = fmaf(2.0f, t, KC);
            float Q = fmaf(18.0f, Sxy, fmaf(-2.0f, t, KC9));
            float R = fmaf(Sx, Sx, fmaf(Sy, Sy, KC));
            float T = Sq + (KC - (Sx + Sy));
            float ratio = __fdividef(P * Q, R * T);
            float ns = fmaf(ratio, -(1.0f / 18.0f), 0.5f);
            ns = fminf(fmaxf(ns, 0.0f), 1.0f);

            acc[h] = fmaf(0.425f, ns, fmaf(0.15f, fabsf(dv_prev), acc[h]));
            dv_prev = v1.x - v1.y;   // becomes center at h+1
        }
    }

    // Combine and write (coalesced per warp-row)
    float* __restrict__ ob = out + (size_t)b * HW;
#pragma unroll
    for (int h = 0; h < RPT; h++) {
        int gr = h0 + row_base + h;
        ob[gr * Wd + w0 + col] = acc[h] * (1.0f / 3.0f);
    }
}

extern "C" void kernel_launch(void* const* d_in, const int* in_sizes, int n_in,
                              void* d_out, int out_size) {
    const float* X = (const float*)d_in[0];   // output
    const float* Y = (const float*)d_in[1];   // target
    float* O = (float*)d_out;

    dim3 grid(Wd / TW, Hd / TH, Bn);   // 5 x 24 x 32
    dim3 block(256);
    recon_loss_kernel<<<grid, block>>>(X, Y, O);
}